// round 3
// baseline (speedup 1.0000x reference)
#include <cuda_runtime.h>
#include <math.h>

#define NB    16
#define NS    512
#define NBINS 511

// Scratch: row-FFT output spectra. [sig][batch][row][col], sig0 = Ft, sig1 = Fe.
__device__ float2 g_spec[2][NB][NS][NS];           // 64 MiB
// Per-(batch, bin) power accumulators (bin 511 = overflow, dropped).
__device__ double g_ns[NB * 512];
__device__ double g_es[NB * 512];

__device__ __forceinline__ unsigned brev9(unsigned x) { return __brev(x) >> 23; }

// In-place 512-point radix-2 DIT FFT. a[] must be loaded in bit-reversed order.
// Called by all 256 threads of the block; t = threadIdx.x.
__device__ __forceinline__ void fft512(float2* a, int t) {
#pragma unroll
    for (int s = 1; s <= 9; s++) {
        const int half = 1 << (s - 1);
        const int j    = t & (half - 1);
        const int i0   = ((t & ~(half - 1)) << 1) | j;
        const int i1   = i0 + half;
        float sw, cw;
        __sincosf(-6.283185307179586f * (float)j / (float)(1 << s), &sw, &cw);
        float2 u = a[i0];
        float2 v = a[i1];
        float vr = v.x * cw - v.y * sw;
        float vi = v.x * sw + v.y * cw;
        a[i0] = make_float2(u.x + vr, u.y + vi);
        a[i1] = make_float2(u.x - vr, u.y - vi);
        __syncthreads();
    }
}

__global__ void zero_acc_kernel() {
    int i = blockIdx.x * blockDim.x + threadIdx.x;
    if (i < NB * 512) { g_ns[i] = 0.0; g_es[i] = 0.0; }
}

// One block per (row, batch, sig). Row FFT of tc (sig 0) or zc - tc (sig 1).
__global__ __launch_bounds__(256) void row_fft_kernel(const float* __restrict__ z,
                                                      const float* __restrict__ tt) {
    __shared__ float2 a[NS];
    const int row = blockIdx.x, b = blockIdx.y, sig = blockIdx.z;
    const int t = threadIdx.x;
    const size_t base = ((size_t)b * NS + row) * NS;
    const float2* zp = (const float2*)z + base;
    const float2* tp = (const float2*)tt + base;

    for (int k = t; k < NS; k += 256) {
        float2 tv = tp[k];
        float2 val;
        if (sig == 0) {
            val = tv;
        } else {
            float2 zv = zp[k];
            val = make_float2(zv.x - tv.x, zv.y - tv.y);
        }
        a[brev9(k)] = val;
    }
    __syncthreads();
    fft512(a, t);

    float2* out = &g_spec[sig][b][row][0];
    for (int k = t; k < NS; k += 256) out[k] = a[k];
}

// One block per (col, batch, sig). Column FFT + power + radial-bin accumulate.
__global__ __launch_bounds__(256) void col_fft_kernel() {
    __shared__ float2 a[NS];
    const int v = blockIdx.x, b = blockIdx.y, sig = blockIdx.z;
    const int t = threadIdx.x;

    for (int u = t; u < NS; u += 256) a[brev9(u)] = g_spec[sig][b][u][v];
    __syncthreads();
    fft512(a, t);

    double* acc = (sig == 0) ? g_ns : g_es;
    const int dv = v - 256;
    for (int u = t; u < NS; u += 256) {
        float2 x = a[u];
        float p = x.x * x.x + x.y * x.y;
        int du = u - 256;
        int s2 = du * du + dv * dv;
        // bin = searchsorted(r2, ellipse, 'right') == floor(511*sqrt(s2)/256),
        // exact in double (min gap to any boundary >= 3e-8; only tie is s2=65536
        // which lands exactly on bin 511 = overflow, dropped).
        int bin = (int)(511.0 * sqrt((double)s2) * (1.0 / 256.0));
        if (bin > 511) bin = 511;
        atomicAdd(&acc[b * 512 + bin], (double)p);
    }
}

__global__ void reduce_kernel(float* __restrict__ out) {
    __shared__ double sh[256];
    const int t = threadIdx.x;
    double s = 0.0;
    for (int i = t; i < NB * 512; i += 256) {
        int bin = i & 511;
        if (bin < NBINS) {
            double ns = g_ns[i];
            double es = g_es[i];
            s += es / fmax(ns, 1e-8);
        }
    }
    sh[t] = s;
    __syncthreads();
    for (int k = 128; k > 0; k >>= 1) {
        if (t < k) sh[t] += sh[t + k];
        __syncthreads();
    }
    if (t == 0) out[0] = (float)(sh[0] / (double)NB);
}

extern "C" void kernel_launch(void* const* d_in, const int* in_sizes, int n_in,
                              void* d_out, int out_size) {
    const float* z  = (const float*)d_in[0];   // z_ [16,512,512,2]
    const float* tt = (const float*)d_in[1];   // t_ [16,512,512,2]
    float* out = (float*)d_out;
    (void)in_sizes; (void)n_in; (void)out_size;

    zero_acc_kernel<<<(NB * 512 + 255) / 256, 256>>>();
    {
        dim3 grid(NS, NB, 2);
        row_fft_kernel<<<grid, 256>>>(z, tt);
    }
    {
        dim3 grid(NS, NB, 2);
        col_fft_kernel<<<grid, 256>>>();
    }
    reduce_kernel<<<1, 256>>>(out);
}

// round 4
// speedup vs baseline: 2.8130x; 2.8130x over previous
#include <cuda_runtime.h>
#include <math.h>

#define NB    16
#define NS    512
#define NBINS 511
#define TILE_V 8
#define NT    (NS / TILE_V)   // 64 column tiles

// Transposed row-FFT spectra: [sig][batch][pos(v, bit-rev order)][row]. 67 MB.
__device__ float2 g_specT[2][NB][NS][NS];
// Per-(sig, batch, tile) partial shell sums (float). 16.8 MB.
__device__ float  g_part[2][NB][NT][512];
// Bin table indexed by [pos][k] with both bit-reversals baked in. 512 KB.
__device__ unsigned short g_tab[NS * NS];
__device__ double g_bsum[NB];

__device__ __forceinline__ unsigned brev9(unsigned x) { return __brev(x) >> 23; }

// In-place 512-point radix-2 DIF FFT: natural-order input, bit-reversed output.
// Executed by 256 butterfly threads (t = 0..255); __syncthreads is block-wide,
// so all co-resident engines must run the same stage count (they do).
__device__ __forceinline__ void fft512_dif(float2* a, int t) {
#pragma unroll
    for (int s = 9; s >= 1; s--) {
        const int half = 1 << (s - 1);
        const int j    = t & (half - 1);
        const int i0   = ((t & ~(half - 1)) << 1) | j;
        const int i1   = i0 + half;
        float sw, cw;
        __sincosf(-6.283185307179586f * (float)j / (float)(1 << s), &sw, &cw);
        float2 u = a[i0];
        float2 v = a[i1];
        float dr = u.x - v.x, di = u.y - v.y;
        a[i0] = make_float2(u.x + v.x, u.y + v.y);
        a[i1] = make_float2(dr * cw - di * sw, dr * sw + di * cw);
        __syncthreads();
    }
}

// Bin table: position k of a DIF output is frequency brev(k); column storage
// position pos is frequency brev(pos). bin = floor(511*sqrt(du^2+dv^2)/256),
// exact in double (verified round 2: rel_err 0.0), bin 511 = overflow.
__global__ void tab_kernel() {
    const int pos = blockIdx.x, k = threadIdx.x;
    const int du = (int)brev9(k)   - 256;
    const int dv = (int)brev9(pos) - 256;
    const int s2 = du * du + dv * dv;
    int bin = (int)(511.0 * sqrt((double)s2) * (1.0 / 256.0));
    if (bin > 511) bin = 511;
    g_tab[pos * NS + k] = (unsigned short)bin;
}

// One block per (row, batch): both signals (t and z-t) as two 256-thread FFT
// engines. Coalesced input loads; transposed (strided) output stores.
__global__ __launch_bounds__(512) void row_fft_kernel(const float* __restrict__ z,
                                                      const float* __restrict__ tt) {
    __shared__ float2 w0[NS];
    __shared__ float2 w1[NS];
    const int row = blockIdx.x, b = blockIdx.y;
    const int t = threadIdx.x;
    const size_t base = ((size_t)b * NS + row) * NS;

    float2 tv = ((const float2*)tt)[base + t];
    float2 zv = ((const float2*)z)[base + t];
    w0[t] = tv;                                      // target
    w1[t] = make_float2(zv.x - tv.x, zv.y - tv.y);   // error
    __syncthreads();

    float2* arr = (t < 256) ? w0 : w1;
    fft512_dif(arr, t & 255);

    g_specT[0][b][t][row] = w0[t];
    g_specT[1][b][t][row] = w1[t];
}

// One block per (8-column tile, batch, sig): coalesced column loads, DIF FFT,
// power -> shared float bins (shared atomics only), one partial flush.
__global__ __launch_bounds__(256) void col_fft_kernel() {
    __shared__ float2 w[NS];
    __shared__ float  bins[512];
    const int tile = blockIdx.x, b = blockIdx.y, sig = blockIdx.z;
    const int t = threadIdx.x;

    bins[t]       = 0.0f;
    bins[t + 256] = 0.0f;

    for (int c = 0; c < TILE_V; c++) {
        const int pos = tile * TILE_V + c;
        const float2* __restrict__ src = &g_specT[sig][b][pos][0];
        w[t]       = src[t];
        w[t + 256] = src[t + 256];
        __syncthreads();                 // also covers bins init on c==0

        fft512_dif(w, t);                // ends with __syncthreads

        const unsigned short* __restrict__ tb = &g_tab[pos * NS];
        float2 x = w[t];
        atomicAdd(&bins[tb[t]],       x.x * x.x + x.y * x.y);
        float2 y = w[t + 256];
        atomicAdd(&bins[tb[t + 256]], y.x * y.x + y.y * y.y);
        __syncthreads();                 // w reuse + final flush safety
    }

    g_part[sig][b][tile][t]       = bins[t];
    g_part[sig][b][tile][t + 256] = bins[t + 256];
}

// One block per batch: sum partials per bin, ratio, block-reduce.
__global__ __launch_bounds__(512) void reduce1_kernel() {
    __shared__ double sh[512];
    const int b = blockIdx.x, t = threadIdx.x;
    double ns = 0.0, es = 0.0;
#pragma unroll 8
    for (int tile = 0; tile < NT; tile++) {
        ns += (double)g_part[0][b][tile][t];
        es += (double)g_part[1][b][tile][t];
    }
    sh[t] = (t < NBINS) ? es / fmax(ns, 1e-8) : 0.0;
    __syncthreads();
    for (int k = 256; k > 0; k >>= 1) {
        if (t < k) sh[t] += sh[t + k];
        __syncthreads();
    }
    if (t == 0) g_bsum[b] = sh[0];
}

__global__ void reduce2_kernel(float* __restrict__ out) {
    double s = 0.0;
#pragma unroll
    for (int i = 0; i < NB; i++) s += g_bsum[i];
    out[0] = (float)(s / (double)NB);
}

extern "C" void kernel_launch(void* const* d_in, const int* in_sizes, int n_in,
                              void* d_out, int out_size) {
    const float* z  = (const float*)d_in[0];   // z_ [16,512,512,2]
    const float* tt = (const float*)d_in[1];   // t_ [16,512,512,2]
    float* out = (float*)d_out;
    (void)in_sizes; (void)n_in; (void)out_size;

    tab_kernel<<<NS, NS>>>();
    {
        dim3 grid(NS, NB);
        row_fft_kernel<<<grid, 512>>>(z, tt);
    }
    {
        dim3 grid(NT, NB, 2);
        col_fft_kernel<<<grid, 256>>>();
    }
    reduce1_kernel<<<NB, 512>>>();
    reduce2_kernel<<<1, 1>>>(out);
}

// round 5
// speedup vs baseline: 3.3547x; 1.1926x over previous
#include <cuda_runtime.h>
#include <math.h>

#define NB    16
#define NS    512
#define NBINS 511
#define TILE_V 8
#define NT    (NS / TILE_V)   // 64 column tiles

// Transposed row-FFT spectra: [sig][batch][pos][row]. 67 MB.
__device__ float2 g_specT[2][NB][NS][NS];
// Per-(sig, batch, tile) partial shell sums. 4 MB.
__device__ float  g_part[2][NB][NT][512];
// Stage-2 partials for the reduction tree.
__device__ float  g_p2[2][NB][8][512];
// Bin table [pos][k] with bit-reversal baked in. 512 KB.
__device__ unsigned short g_tab[NS * NS];
// Twiddle table, per-stage contiguous: segment for stage `half` starts at
// offset 512 - 2*half and holds W_{2*half}^j, j = 0..half-1.
__device__ float2 g_twk[512];
__device__ double g_bsum[NB];

__device__ __forceinline__ unsigned brev9(unsigned x) { return __brev(x) >> 23; }

// ---------------- setup kernels ----------------

__global__ void twk_kernel() {
    const int i = threadIdx.x;
#pragma unroll
    for (int half = 256; half >= 1; half >>= 1) {
        const int off = 512 - 2 * half;
        if (i >= off && i < off + half) {
            const int j = i - off;
            double ang = -6.283185307179586476925287 * (double)j / (double)(2 * half);
            g_twk[i] = make_float2((float)cos(ang), (float)sin(ang));
        }
    }
}

// bin = floor(511*sqrt(du^2+dv^2)/256), exact in double (verified: rel_err 0.0).
__global__ void tab_kernel() {
    const int pos = blockIdx.x, k = threadIdx.x;
    const int du = (int)brev9(k)   - 256;
    const int dv = (int)brev9(pos) - 256;
    const int s2 = du * du + dv * dv;
    int bin = (int)(511.0 * sqrt((double)s2) * (1.0 / 256.0));
    if (bin > 511) bin = 511;
    g_tab[pos * NS + k] = (unsigned short)bin;
}

// ---------------- FFT helpers ----------------

__device__ __forceinline__ float2 cadd(float2 a, float2 b) {
    return make_float2(a.x + b.x, a.y + b.y);
}
// (u - v) * tw
__device__ __forceinline__ float2 csubmul(float2 u, float2 v, float2 tw) {
    float dr = u.x - v.x, di = u.y - v.y;
    return make_float2(dr * tw.x - di * tw.y, dr * tw.y + di * tw.x);
}

// Smem radix-2 DIF stages half = 256..32 (conflict-free). 256 threads per engine.
__device__ __forceinline__ void fft_smem_stages(float2* w, const float2* s_tw, int t) {
#pragma unroll
    for (int half = 256; half >= 32; half >>= 1) {
        const int j  = t & (half - 1);
        const int i0 = ((t & ~(half - 1)) << 1) | j;
        const float2 tw = s_tw[512 - 2 * half + j];
        float2 u = w[i0];
        float2 v = w[i0 + half];
        w[i0]        = cadd(u, v);
        w[i0 + half] = csubmul(u, v, tw);
        __syncthreads();
    }
}

// Register-phase butterfly (stages half = 16..1) via warp shuffle.
__device__ __forceinline__ float2 bfly_shfl(float2 x, int half, float2 tw, int L) {
    float px = __shfl_xor_sync(0xffffffffu, x.x, half);
    float py = __shfl_xor_sync(0xffffffffu, x.y, half);
    if ((L & half) == 0)
        return make_float2(x.x + px, x.y + py);
    float dr = px - x.x, di = py - x.y;
    return make_float2(dr * tw.x - di * tw.y, dr * tw.y + di * tw.x);
}

// Finish the last 5 stages in registers. Lane L holds window positions
// 64*wk + L (x0) and 64*wk + 32 + L (x1); layout identical to pure radix-2
// DIF, so output position p holds frequency brev9(p).
__device__ __forceinline__ void fft_reg_stages(float2& x0, float2& x1,
                                               const float2* s_tw, int L) {
#pragma unroll
    for (int half = 16; half >= 1; half >>= 1) {
        const float2 tw = s_tw[512 - 2 * half + (L & (half - 1))];
        x0 = bfly_shfl(x0, half, tw, L);
        x1 = bfly_shfl(x1, half, tw, L);
    }
}

// ---------------- main kernels ----------------

// One block per (row, batch): two 256-thread FFT engines (sig 0 = t, sig 1 = z-t).
__global__ __launch_bounds__(512) void row_fft_kernel(const float* __restrict__ z,
                                                      const float* __restrict__ tt) {
    __shared__ float2 w0[NS];
    __shared__ float2 w1[NS];
    __shared__ float2 s_tw[512];
    const int row = blockIdx.x, b = blockIdx.y;
    const int t = threadIdx.x;

    s_tw[t] = g_twk[t];

    const size_t base = ((size_t)b * NS + row) * NS;
    float2 tv = ((const float2*)tt)[base + t];
    float2 zv = ((const float2*)z)[base + t];
    w0[t] = tv;
    w1[t] = make_float2(zv.x - tv.x, zv.y - tv.y);
    __syncthreads();

    const int sig = t >> 8;
    const int te  = t & 255;
    float2* w = (sig == 0) ? w0 : w1;

    fft_smem_stages(w, s_tw, te);

    const int wk = te >> 5;          // window pair within engine
    const int L  = t & 31;           // lane
    const int p0 = (wk << 6) + L;
    const int p1 = p0 + 32;
    float2 x0 = w[p0];
    float2 x1 = w[p1];
    fft_reg_stages(x0, x1, s_tw, L);

    g_specT[sig][b][p0][row] = x0;
    g_specT[sig][b][p1][row] = x1;
}

// One block per (8-column tile, batch, sig): coalesced loads, hybrid FFT,
// power -> shared float bins, one partial flush per block.
__global__ __launch_bounds__(256) void col_fft_kernel() {
    __shared__ float2 w[NS];
    __shared__ float2 s_tw[512];
    __shared__ float  bins[512];
    const int tile = blockIdx.x, b = blockIdx.y, sig = blockIdx.z;
    const int t = threadIdx.x;

    s_tw[t]       = g_twk[t];
    s_tw[t + 256] = g_twk[t + 256];
    bins[t]       = 0.0f;
    bins[t + 256] = 0.0f;

    const int wk = t >> 5;
    const int L  = t & 31;
    const int p0 = (wk << 6) + L;
    const int p1 = p0 + 32;

    for (int c = 0; c < TILE_V; c++) {
        const int pos = tile * TILE_V + c;
        const float2* __restrict__ src = &g_specT[sig][b][pos][0];
        w[t]       = src[t];
        w[t + 256] = src[t + 256];
        __syncthreads();                 // also covers s_tw/bins init on c==0

        fft_smem_stages(w, s_tw, t);     // ends with __syncthreads

        float2 x0 = w[p0];
        float2 x1 = w[p1];
        fft_reg_stages(x0, x1, s_tw, L);

        const unsigned short* __restrict__ tb = &g_tab[pos * NS];
        atomicAdd(&bins[tb[p0]], x0.x * x0.x + x0.y * x0.y);
        atomicAdd(&bins[tb[p1]], x1.x * x1.x + x1.y * x1.y);
        __syncthreads();                 // w reuse next iteration
    }

    g_part[sig][b][tile][t]       = bins[t];
    g_part[sig][b][tile][t + 256] = bins[t + 256];
}

// ---------------- reduction tree ----------------

// Stage A: (NB x 8) blocks, each sums 8 tiles for both signals.
__global__ __launch_bounds__(512) void reduce1a_kernel() {
    const int b = blockIdx.x, g = blockIdx.y, t = threadIdx.x;
    float ns = 0.0f, es = 0.0f;
#pragma unroll
    for (int tl = 0; tl < 8; tl++) {
        ns += g_part[0][b][g * 8 + tl][t];
        es += g_part[1][b][g * 8 + tl][t];
    }
    g_p2[0][b][g][t] = ns;
    g_p2[1][b][g][t] = es;
}

// Stage B: per-batch ratio + block reduce.
__global__ __launch_bounds__(512) void reduce1b_kernel() {
    __shared__ double sh[512];
    const int b = blockIdx.x, t = threadIdx.x;
    double ns = 0.0, es = 0.0;
#pragma unroll
    for (int g = 0; g < 8; g++) {
        ns += (double)g_p2[0][b][g][t];
        es += (double)g_p2[1][b][g][t];
    }
    sh[t] = (t < NBINS) ? es / fmax(ns, 1e-8) : 0.0;
    __syncthreads();
    for (int k = 256; k > 0; k >>= 1) {
        if (t < k) sh[t] += sh[t + k];
        __syncthreads();
    }
    if (t == 0) g_bsum[b] = sh[0];
}

__global__ void reduce2_kernel(float* __restrict__ out) {
    double s = 0.0;
#pragma unroll
    for (int i = 0; i < NB; i++) s += g_bsum[i];
    out[0] = (float)(s / (double)NB);
}

extern "C" void kernel_launch(void* const* d_in, const int* in_sizes, int n_in,
                              void* d_out, int out_size) {
    const float* z  = (const float*)d_in[0];   // z_ [16,512,512,2]
    const float* tt = (const float*)d_in[1];   // t_ [16,512,512,2]
    float* out = (float*)d_out;
    (void)in_sizes; (void)n_in; (void)out_size;

    twk_kernel<<<1, 512>>>();
    tab_kernel<<<NS, NS>>>();
    {
        dim3 grid(NS, NB);
        row_fft_kernel<<<grid, 512>>>(z, tt);
    }
    {
        dim3 grid(NT, NB, 2);
        col_fft_kernel<<<grid, 256>>>();
    }
    {
        dim3 grid(NB, 8);
        reduce1a_kernel<<<grid, 512>>>();
    }
    reduce1b_kernel<<<NB, 512>>>();
    reduce2_kernel<<<1, 1>>>(out);
}

// round 6
// speedup vs baseline: 3.9018x; 1.1631x over previous
#include <cuda_runtime.h>
#include <math.h>

#define NB    16
#define NS    512
#define NBINS 511
#define TILE_V 8
#define NT    (NS / TILE_V)   // 64 column tiles

// Transposed row-FFT spectra: [sig][batch][pos][row]. 67 MB.
__device__ float2 g_specT[2][NB][NS][NS];
// Per-(sig, batch, tile) partial shell sums. 4 MB.
__device__ float  g_part[2][NB][NT][512];
// Stage-2 partials for the reduction tree.
__device__ float  g_p2[2][NB][8][512];
// Bin table [pos][k] with bit-reversal baked in. 512 KB.
__device__ unsigned short g_tab[NS * NS];
// Twiddle table, per-stage contiguous: segment for stage `half` starts at
// offset 512 - 2*half and holds W_{2*half}^j, j = 0..half-1.
__device__ float2 g_twk[512];
__device__ double g_bsum[NB];

__device__ __forceinline__ unsigned brev9(unsigned x) { return __brev(x) >> 23; }

// ---------------- setup kernels ----------------

__global__ void twk_kernel() {
    const int i = threadIdx.x;
#pragma unroll
    for (int half = 256; half >= 1; half >>= 1) {
        const int off = 512 - 2 * half;
        if (i >= off && i < off + half) {
            const int j = i - off;
            double ang = -6.283185307179586476925287 * (double)j / (double)(2 * half);
            g_twk[i] = make_float2((float)cos(ang), (float)sin(ang));
        }
    }
}

// bin = floor(511*sqrt(du^2+dv^2)/256), exact in double (verified: rel_err 0.0).
__global__ void tab_kernel() {
    const int pos = blockIdx.x, k = threadIdx.x;
    const int du = (int)brev9(k)   - 256;
    const int dv = (int)brev9(pos) - 256;
    const int s2 = du * du + dv * dv;
    int bin = (int)(511.0 * sqrt((double)s2) * (1.0 / 256.0));
    if (bin > 511) bin = 511;
    g_tab[pos * NS + k] = (unsigned short)bin;
}

// ---------------- FFT helpers ----------------

__device__ __forceinline__ float2 cadd(float2 a, float2 b) {
    return make_float2(a.x + b.x, a.y + b.y);
}
// (u - v) * tw
__device__ __forceinline__ float2 csubmul(float2 u, float2 v, float2 tw) {
    float dr = u.x - v.x, di = u.y - v.y;
    return make_float2(dr * tw.x - di * tw.y, dr * tw.y + di * tw.x);
}

// Two fused radix-2 DIF stage-layers (block sizes 4h then 2h) on one group of 4.
// Inputs a..d at positions p, p+h, p+2h, p+3h; outputs o0..o3 to the same slots.
// tw1 = W_{4h}^j, tw1b = W_{4h}^{j+h}, tw2 = W_{2h}^j   (j = p mod h... per caller)
__device__ __forceinline__ void r4dif(float2 a, float2 b, float2 c, float2 d,
                                      float2 tw1, float2 tw1b, float2 tw2,
                                      float2& o0, float2& o1, float2& o2, float2& o3) {
    float2 t0 = cadd(a, c);
    float2 t1 = csubmul(a, c, tw1);
    float2 t2 = cadd(b, d);
    float2 t3 = csubmul(b, d, tw1b);
    o0 = cadd(t0, t2);
    o1 = csubmul(t0, t2, tw2);
    o2 = cadd(t1, t3);
    o3 = csubmul(t1, t3, tw2);
}

// Register-phase butterfly (stages half = 16..1) via warp shuffle.
__device__ __forceinline__ float2 bfly_shfl(float2 x, int half, float2 tw, int L) {
    float px = __shfl_xor_sync(0xffffffffu, x.x, half);
    float py = __shfl_xor_sync(0xffffffffu, x.y, half);
    if ((L & half) == 0)
        return make_float2(x.x + px, x.y + py);
    float dr = px - x.x, di = py - x.y;
    return make_float2(dr * tw.x - di * tw.y, dr * tw.y + di * tw.x);
}

// Last 5 stages (half 16..1) for 4 register-resident points at positions
// pb, pb+32, pb+64, pb+96 (pb = 128*ww + L). Butterflies stay inside
// 32-element windows, so each point only needs intra-warp shuffles.
__device__ __forceinline__ void fft_reg_stages4(float2& x0, float2& x1,
                                                float2& x2, float2& x3,
                                                const float2* s_tw, int L) {
#pragma unroll
    for (int half = 16; half >= 1; half >>= 1) {
        const float2 tw = s_tw[512 - 2 * half + (L & (half - 1))];
        x0 = bfly_shfl(x0, half, tw, L);
        x1 = bfly_shfl(x1, half, tw, L);
        x2 = bfly_shfl(x2, half, tw, L);
        x3 = bfly_shfl(x3, half, tw, L);
    }
}

// ---------------- main kernels ----------------

// One block per (row, batch). 256 threads = 2 signal engines x 128 threads.
// Single smem round-trip between radix-4 pass A and pass B.
__global__ __launch_bounds__(256) void row_fft_kernel(const float* __restrict__ z,
                                                      const float* __restrict__ tt) {
    __shared__ float2 w[2][NS];     // [sig][...] exchange buffer
    __shared__ float2 s_tw[512];
    const int row = blockIdx.x, b = blockIdx.y;
    const int t = threadIdx.x;

    s_tw[t]       = g_twk[t];
    s_tw[t + 256] = g_twk[t + 256];

    const int f  = t >> 7;          // signal: 0 = target, 1 = error
    const int g  = t & 127;         // group within FFT
    const int L  = t & 31;
    const int ww = g >> 5;
    const int pb = 128 * ww + L;    // register-phase base position

    const size_t base = ((size_t)b * NS + row) * NS;
    const float2* __restrict__ tp = (const float2*)tt + base;
    const float2* __restrict__ zp = (const float2*)z  + base;

    float2 a0 = tp[g], a1 = tp[g + 128], a2 = tp[g + 256], a3 = tp[g + 384];
    if (f == 1) {
        float2 z0 = zp[g], z1 = zp[g + 128], z2 = zp[g + 256], z3 = zp[g + 384];
        a0 = make_float2(z0.x - a0.x, z0.y - a0.y);
        a1 = make_float2(z1.x - a1.x, z1.y - a1.y);
        a2 = make_float2(z2.x - a2.x, z2.y - a2.y);
        a3 = make_float2(z3.x - a3.x, z3.y - a3.y);
    }
    __syncthreads();                // s_tw ready

    // Pass A: stages half = 256, 128 on {g, g+128, g+256, g+384}
    float2 o0, o1, o2, o3;
    r4dif(a0, a1, a2, a3, s_tw[g], s_tw[g + 128], s_tw[256 + g], o0, o1, o2, o3);
    float2* wf = w[f];
    wf[g] = o0; wf[g + 128] = o1; wf[g + 256] = o2; wf[g + 384] = o3;
    __syncthreads();

    // Pass B: stages half = 64, 32 on {pb, pb+32, pb+64, pb+96}.
    // Outputs land exactly at this thread's register-phase slots: no store-back.
    float2 b0 = wf[pb], b1 = wf[pb + 32], b2 = wf[pb + 64], b3 = wf[pb + 96];
    float2 x0, x1, x2, x3;
    r4dif(b0, b1, b2, b3, s_tw[384 + L], s_tw[416 + L], s_tw[448 + L], x0, x1, x2, x3);
    fft_reg_stages4(x0, x1, x2, x3, s_tw, L);

    g_specT[f][b][pb][row]      = x0;
    g_specT[f][b][pb + 32][row] = x1;
    g_specT[f][b][pb + 64][row] = x2;
    g_specT[f][b][pb + 96][row] = x3;
}

// One block per (8-col tile, batch, sig). 256 threads = 2 column engines.
// One barrier per column-pair (double-buffered exchange).
__global__ __launch_bounds__(256) void col_fft_kernel() {
    __shared__ float2 w[2][2 * NS]; // [buf][engine*512 + ...]
    __shared__ float2 s_tw[512];
    __shared__ float  bins[512];
    const int tile = blockIdx.x, b = blockIdx.y, sig = blockIdx.z;
    const int t = threadIdx.x;

    s_tw[t]       = g_twk[t];
    s_tw[t + 256] = g_twk[t + 256];
    bins[t]       = 0.0f;
    bins[t + 256] = 0.0f;

    const int f  = t >> 7;          // column engine 0/1
    const int g  = t & 127;
    const int L  = t & 31;
    const int ww = g >> 5;
    const int pb = 128 * ww + L;
    __syncthreads();                // s_tw + bins ready

#pragma unroll
    for (int c = 0; c < TILE_V; c += 2) {
        const int pos = tile * TILE_V + c + f;
        const float2* __restrict__ src = &g_specT[sig][b][pos][0];

        // Coalesced strided global loads straight into pass A.
        float2 a0 = src[g], a1 = src[g + 128], a2 = src[g + 256], a3 = src[g + 384];
        float2 o0, o1, o2, o3;
        r4dif(a0, a1, a2, a3, s_tw[g], s_tw[g + 128], s_tw[256 + g], o0, o1, o2, o3);

        float2* wf = &w[(c >> 1) & 1][f * NS];
        wf[g] = o0; wf[g + 128] = o1; wf[g + 256] = o2; wf[g + 384] = o3;
        __syncthreads();

        float2 b0 = wf[pb], b1 = wf[pb + 32], b2 = wf[pb + 64], b3 = wf[pb + 96];
        float2 x0, x1, x2, x3;
        r4dif(b0, b1, b2, b3, s_tw[384 + L], s_tw[416 + L], s_tw[448 + L], x0, x1, x2, x3);
        fft_reg_stages4(x0, x1, x2, x3, s_tw, L);

        const unsigned short* __restrict__ tb = &g_tab[pos * NS];
        atomicAdd(&bins[tb[pb]],      x0.x * x0.x + x0.y * x0.y);
        atomicAdd(&bins[tb[pb + 32]], x1.x * x1.x + x1.y * x1.y);
        atomicAdd(&bins[tb[pb + 64]], x2.x * x2.x + x2.y * x2.y);
        atomicAdd(&bins[tb[pb + 96]], x3.x * x3.x + x3.y * x3.y);
    }
    __syncthreads();

    g_part[sig][b][tile][t]       = bins[t];
    g_part[sig][b][tile][t + 256] = bins[t + 256];
}

// ---------------- reduction tree ----------------

__global__ __launch_bounds__(512) void reduce1a_kernel() {
    const int b = blockIdx.x, g = blockIdx.y, t = threadIdx.x;
    float ns = 0.0f, es = 0.0f;
#pragma unroll
    for (int tl = 0; tl < 8; tl++) {
        ns += g_part[0][b][g * 8 + tl][t];
        es += g_part[1][b][g * 8 + tl][t];
    }
    g_p2[0][b][g][t] = ns;
    g_p2[1][b][g][t] = es;
}

__global__ __launch_bounds__(512) void reduce1b_kernel() {
    __shared__ double sh[512];
    const int b = blockIdx.x, t = threadIdx.x;
    double ns = 0.0, es = 0.0;
#pragma unroll
    for (int g = 0; g < 8; g++) {
        ns += (double)g_p2[0][b][g][t];
        es += (double)g_p2[1][b][g][t];
    }
    sh[t] = (t < NBINS) ? es / fmax(ns, 1e-8) : 0.0;
    __syncthreads();
    for (int k = 256; k > 0; k >>= 1) {
        if (t < k) sh[t] += sh[t + k];
        __syncthreads();
    }
    if (t == 0) g_bsum[b] = sh[0];
}

__global__ void reduce2_kernel(float* __restrict__ out) {
    double s = 0.0;
#pragma unroll
    for (int i = 0; i < NB; i++) s += g_bsum[i];
    out[0] = (float)(s / (double)NB);
}

extern "C" void kernel_launch(void* const* d_in, const int* in_sizes, int n_in,
                              void* d_out, int out_size) {
    const float* z  = (const float*)d_in[0];   // z_ [16,512,512,2]
    const float* tt = (const float*)d_in[1];   // t_ [16,512,512,2]
    float* out = (float*)d_out;
    (void)in_sizes; (void)n_in; (void)out_size;

    twk_kernel<<<1, 512>>>();
    tab_kernel<<<NS, NS>>>();
    {
        dim3 grid(NS, NB);
        row_fft_kernel<<<grid, 256>>>(z, tt);
    }
    {
        dim3 grid(NT, NB, 2);
        col_fft_kernel<<<grid, 256>>>();
    }
    {
        dim3 grid(NB, 8);
        reduce1a_kernel<<<grid, 512>>>();
    }
    reduce1b_kernel<<<NB, 512>>>();
    reduce2_kernel<<<1, 1>>>(out);
}

// round 7
// speedup vs baseline: 4.4910x; 1.1510x over previous
#include <cuda_runtime.h>
#include <math.h>

#define NB    16
#define NS    512
#define NBINS 511
#define TILE_V 8
#define NT    (NS / TILE_V)   // 64 column tiles
#define RROWS 4               // rows per block in row_fft (32B-sector transpose)

// Transposed row-FFT spectra: [sig][batch][pos][row]. 67 MB.
__device__ float2 g_specT[2][NB][NS][NS];
// Per-(sig, batch, tile) partial shell sums. 4 MB.
__device__ float  g_part[2][NB][NT][512];
// Stage-2 partials for the reduction tree.
__device__ float  g_p2[2][NB][8][512];
// Bin table [pos][k] with bit-reversal baked in. 512 KB.
__device__ unsigned short g_tab[NS * NS];
// Twiddle table, per-stage contiguous: segment for stage `half` starts at
// offset 512 - 2*half and holds W_{2*half}^j, j = 0..half-1.
__device__ float2 g_twk[512];
__device__ double g_bsum[NB];

__device__ __forceinline__ unsigned brev9(unsigned x) { return __brev(x) >> 23; }

// ---------------- setup kernels ----------------

__global__ void twk_kernel() {
    const int i = threadIdx.x;
#pragma unroll
    for (int half = 256; half >= 1; half >>= 1) {
        const int off = 512 - 2 * half;
        if (i >= off && i < off + half) {
            const int j = i - off;
            double ang = -6.283185307179586476925287 * (double)j / (double)(2 * half);
            g_twk[i] = make_float2((float)cos(ang), (float)sin(ang));
        }
    }
}

// bin = floor(511*sqrt(du^2+dv^2)/256), exact in double (verified: rel_err 0.0).
__global__ void tab_kernel() {
    const int pos = blockIdx.x, k = threadIdx.x;
    const int du = (int)brev9(k)   - 256;
    const int dv = (int)brev9(pos) - 256;
    const int s2 = du * du + dv * dv;
    int bin = (int)(511.0 * sqrt((double)s2) * (1.0 / 256.0));
    if (bin > 511) bin = 511;
    g_tab[pos * NS + k] = (unsigned short)bin;
}

// ---------------- FFT helpers ----------------

__device__ __forceinline__ float2 cadd(float2 a, float2 b) {
    return make_float2(a.x + b.x, a.y + b.y);
}
// (u - v) * tw
__device__ __forceinline__ float2 csubmul(float2 u, float2 v, float2 tw) {
    float dr = u.x - v.x, di = u.y - v.y;
    return make_float2(dr * tw.x - di * tw.y, dr * tw.y + di * tw.x);
}

// Two fused radix-2 DIF stage-layers (block sizes 4h then 2h) on one group of 4.
__device__ __forceinline__ void r4dif(float2 a, float2 b, float2 c, float2 d,
                                      float2 tw1, float2 tw1b, float2 tw2,
                                      float2& o0, float2& o1, float2& o2, float2& o3) {
    float2 t0 = cadd(a, c);
    float2 t1 = csubmul(a, c, tw1);
    float2 t2 = cadd(b, d);
    float2 t3 = csubmul(b, d, tw1b);
    o0 = cadd(t0, t2);
    o1 = csubmul(t0, t2, tw2);
    o2 = cadd(t1, t3);
    o3 = csubmul(t1, t3, tw2);
}

// Generic shuffle butterfly for half = 16, 8, 4 (twiddle in register).
__device__ __forceinline__ float2 bfly_shfl(float2 x, int half, float2 tw, int L) {
    float px = __shfl_xor_sync(0xffffffffu, x.x, half);
    float py = __shfl_xor_sync(0xffffffffu, x.y, half);
    if ((L & half) == 0)
        return make_float2(x.x + px, x.y + py);
    float dr = px - x.x, di = py - x.y;
    return make_float2(dr * tw.x - di * tw.y, dr * tw.y + di * tw.x);
}

// half = 2: twiddle is W_4^{L&1} = (1,0) or (0,-1) -> swap/negate, no FMA chain.
__device__ __forceinline__ float2 bfly_h2(float2 x, int L) {
    float px = __shfl_xor_sync(0xffffffffu, x.x, 2);
    float py = __shfl_xor_sync(0xffffffffu, x.y, 2);
    if ((L & 2) == 0) return make_float2(x.x + px, x.y + py);
    float dr = px - x.x, di = py - x.y;
    return (L & 1) ? make_float2(di, -dr) : make_float2(dr, di);
}

// half = 1: twiddle is (1,0) -> plain add/sub.
__device__ __forceinline__ float2 bfly_h1(float2 x, int L) {
    float px = __shfl_xor_sync(0xffffffffu, x.x, 1);
    float py = __shfl_xor_sync(0xffffffffu, x.y, 1);
    if ((L & 1) == 0) return make_float2(x.x + px, x.y + py);
    return make_float2(px - x.x, py - x.y);
}

// Last 5 stages (half 16..1) for 4 register-resident points at positions
// pb, pb+32, pb+64, pb+96. All twiddles pre-hoisted into registers.
__device__ __forceinline__ void fft_reg_stages4(float2& x0, float2& x1,
                                                float2& x2, float2& x3,
                                                float2 tw16, float2 tw8, float2 tw4,
                                                int L) {
    x0 = bfly_shfl(x0, 16, tw16, L); x1 = bfly_shfl(x1, 16, tw16, L);
    x2 = bfly_shfl(x2, 16, tw16, L); x3 = bfly_shfl(x3, 16, tw16, L);
    x0 = bfly_shfl(x0, 8, tw8, L);   x1 = bfly_shfl(x1, 8, tw8, L);
    x2 = bfly_shfl(x2, 8, tw8, L);   x3 = bfly_shfl(x3, 8, tw8, L);
    x0 = bfly_shfl(x0, 4, tw4, L);   x1 = bfly_shfl(x1, 4, tw4, L);
    x2 = bfly_shfl(x2, 4, tw4, L);   x3 = bfly_shfl(x3, 4, tw4, L);
    x0 = bfly_h2(x0, L); x1 = bfly_h2(x1, L);
    x2 = bfly_h2(x2, L); x3 = bfly_h2(x3, L);
    x0 = bfly_h1(x0, L); x1 = bfly_h1(x1, L);
    x2 = bfly_h1(x2, L); x3 = bfly_h1(x3, L);
}

// ---------------- main kernels ----------------

// One block per (4-row tile, batch). 256 threads = 2 signal engines x 128.
// Outputs staged in smem, then written transposed in full 32B sectors.
__global__ __launch_bounds__(256) void row_fft_kernel(const float* __restrict__ z,
                                                      const float* __restrict__ tt) {
    __shared__ float2 w[2][2][NS];          // [parity][engine][pos]  16 KB
    __shared__ float2 stage[2][RROWS][NS];  // [sig][row][pos]        32 KB
    const int rt = blockIdx.x, b = blockIdx.y;
    const int t = threadIdx.x;
    const int f = t >> 7;          // signal: 0 = target, 1 = error
    const int g = t & 127;
    const int L = t & 31;
    const int ww = g >> 5;
    const int pb = 128 * ww + L;

    // Loop-invariant twiddles (registers).
    const float2 twA0 = g_twk[g],       twA1 = g_twk[g + 128], twA2 = g_twk[256 + g];
    const float2 twB0 = g_twk[384 + L], twB1 = g_twk[416 + L], twB2 = g_twk[448 + L];
    const float2 tw16 = g_twk[480 + (L & 15)];
    const float2 tw8  = g_twk[496 + (L & 7)];
    const float2 tw4  = g_twk[504 + (L & 3)];

#pragma unroll
    for (int r = 0; r < RROWS; r++) {
        const int row = rt * RROWS + r;
        const size_t base = ((size_t)b * NS + row) * NS;
        const float2* __restrict__ tp = (const float2*)tt + base;

        float2 a0 = tp[g], a1 = tp[g + 128], a2 = tp[g + 256], a3 = tp[g + 384];
        if (f == 1) {
            const float2* __restrict__ zp = (const float2*)z + base;
            float2 z0 = zp[g], z1 = zp[g + 128], z2 = zp[g + 256], z3 = zp[g + 384];
            a0 = make_float2(z0.x - a0.x, z0.y - a0.y);
            a1 = make_float2(z1.x - a1.x, z1.y - a1.y);
            a2 = make_float2(z2.x - a2.x, z2.y - a2.y);
            a3 = make_float2(z3.x - a3.x, z3.y - a3.y);
        }

        float2 o0, o1, o2, o3;
        r4dif(a0, a1, a2, a3, twA0, twA1, twA2, o0, o1, o2, o3);
        float2* wf = w[r & 1][f];
        wf[g] = o0; wf[g + 128] = o1; wf[g + 256] = o2; wf[g + 384] = o3;
        __syncthreads();

        float2 b0 = wf[pb], b1 = wf[pb + 32], b2 = wf[pb + 64], b3 = wf[pb + 96];
        float2 x0, x1, x2, x3;
        r4dif(b0, b1, b2, b3, twB0, twB1, twB2, x0, x1, x2, x3);
        fft_reg_stages4(x0, x1, x2, x3, tw16, tw8, tw4, L);

        stage[f][r][pb]      = x0;
        stage[f][r][pb + 32] = x1;
        stage[f][r][pb + 64] = x2;
        stage[f][r][pb + 96] = x3;
    }
    __syncthreads();

    // Cooperative transposed write-out: for each (sig, pos), rows rt*4..rt*4+3
    // are 32 contiguous bytes in g_specT -> two STG.128 per item.
#pragma unroll
    for (int k = 0; k < 4; k++) {
        const int i   = t + k * 256;     // 0..1023
        const int fo  = i >> 9;
        const int pos = i & 511;
        float2 s0 = stage[fo][0][pos];
        float2 s1 = stage[fo][1][pos];
        float2 s2 = stage[fo][2][pos];
        float2 s3 = stage[fo][3][pos];
        float4* dst = (float4*)&g_specT[fo][b][pos][rt * RROWS];
        dst[0] = make_float4(s0.x, s0.y, s1.x, s1.y);
        dst[1] = make_float4(s2.x, s2.y, s3.x, s3.y);
    }
}

// One block per (8-col tile, batch, sig). 256 threads = 2 column engines.
__global__ __launch_bounds__(256) void col_fft_kernel() {
    __shared__ float2 w[2][2 * NS]; // [parity][engine*512 + pos]  16 KB
    __shared__ float  bins[512];
    const int tile = blockIdx.x, b = blockIdx.y, sig = blockIdx.z;
    const int t = threadIdx.x;
    const int f = t >> 7;
    const int g = t & 127;
    const int L = t & 31;
    const int ww = g >> 5;
    const int pb = 128 * ww + L;

    bins[t]       = 0.0f;
    bins[t + 256] = 0.0f;

    const float2 twA0 = g_twk[g],       twA1 = g_twk[g + 128], twA2 = g_twk[256 + g];
    const float2 twB0 = g_twk[384 + L], twB1 = g_twk[416 + L], twB2 = g_twk[448 + L];
    const float2 tw16 = g_twk[480 + (L & 15)];
    const float2 tw8  = g_twk[496 + (L & 7)];
    const float2 tw4  = g_twk[504 + (L & 3)];

#pragma unroll
    for (int c = 0; c < TILE_V; c += 2) {
        const int pos = tile * TILE_V + c + f;
        const float2* __restrict__ src = &g_specT[sig][b][pos][0];

        float2 a0 = src[g], a1 = src[g + 128], a2 = src[g + 256], a3 = src[g + 384];
        float2 o0, o1, o2, o3;
        r4dif(a0, a1, a2, a3, twA0, twA1, twA2, o0, o1, o2, o3);

        float2* wf = &w[(c >> 1) & 1][f * NS];
        wf[g] = o0; wf[g + 128] = o1; wf[g + 256] = o2; wf[g + 384] = o3;
        __syncthreads();        // also covers bins init on first iteration

        float2 b0 = wf[pb], b1 = wf[pb + 32], b2 = wf[pb + 64], b3 = wf[pb + 96];
        float2 x0, x1, x2, x3;
        r4dif(b0, b1, b2, b3, twB0, twB1, twB2, x0, x1, x2, x3);
        fft_reg_stages4(x0, x1, x2, x3, tw16, tw8, tw4, L);

        const unsigned short* __restrict__ tb = &g_tab[pos * NS];
        atomicAdd(&bins[tb[pb]],      x0.x * x0.x + x0.y * x0.y);
        atomicAdd(&bins[tb[pb + 32]], x1.x * x1.x + x1.y * x1.y);
        atomicAdd(&bins[tb[pb + 64]], x2.x * x2.x + x2.y * x2.y);
        atomicAdd(&bins[tb[pb + 96]], x3.x * x3.x + x3.y * x3.y);
    }
    __syncthreads();

    g_part[sig][b][tile][t]       = bins[t];
    g_part[sig][b][tile][t + 256] = bins[t + 256];
}

// ---------------- reduction tree ----------------

__global__ __launch_bounds__(512) void reduce1a_kernel() {
    const int b = blockIdx.x, g = blockIdx.y, t = threadIdx.x;
    float ns = 0.0f, es = 0.0f;
#pragma unroll
    for (int tl = 0; tl < 8; tl++) {
        ns += g_part[0][b][g * 8 + tl][t];
        es += g_part[1][b][g * 8 + tl][t];
    }
    g_p2[0][b][g][t] = ns;
    g_p2[1][b][g][t] = es;
}

__global__ __launch_bounds__(512) void reduce1b_kernel() {
    __shared__ double sh[512];
    const int b = blockIdx.x, t = threadIdx.x;
    double ns = 0.0, es = 0.0;
#pragma unroll
    for (int g = 0; g < 8; g++) {
        ns += (double)g_p2[0][b][g][t];
        es += (double)g_p2[1][b][g][t];
    }
    sh[t] = (t < NBINS) ? es / fmax(ns, 1e-8) : 0.0;
    __syncthreads();
    for (int k = 256; k > 0; k >>= 1) {
        if (t < k) sh[t] += sh[t + k];
        __syncthreads();
    }
    if (t == 0) g_bsum[b] = sh[0];
}

__global__ void reduce2_kernel(float* __restrict__ out) {
    double s = 0.0;
#pragma unroll
    for (int i = 0; i < NB; i++) s += g_bsum[i];
    out[0] = (float)(s / (double)NB);
}

extern "C" void kernel_launch(void* const* d_in, const int* in_sizes, int n_in,
                              void* d_out, int out_size) {
    const float* z  = (const float*)d_in[0];   // z_ [16,512,512,2]
    const float* tt = (const float*)d_in[1];   // t_ [16,512,512,2]
    float* out = (float*)d_out;
    (void)in_sizes; (void)n_in; (void)out_size;

    twk_kernel<<<1, 512>>>();
    tab_kernel<<<NS, NS>>>();
    {
        dim3 grid(NS / RROWS, NB);
        row_fft_kernel<<<grid, 256>>>(z, tt);
    }
    {
        dim3 grid(NT, NB, 2);
        col_fft_kernel<<<grid, 256>>>();
    }
    {
        dim3 grid(NB, 8);
        reduce1a_kernel<<<grid, 512>>>();
    }
    reduce1b_kernel<<<NB, 512>>>();
    reduce2_kernel<<<1, 1>>>(out);
}